// round 1
// baseline (speedup 1.0000x reference)
#include <cuda_runtime.h>
#include <cstdint>

#define BB 16
#define CC 64
#define NPIX 65536          // 256*256
#define NBVEC 4
#define INV_TEMP (1.0f/20.0f)

// ---------------- device scratch (no allocations allowed) ----------------
__device__ float g_raw[BB][CC];                 // selected pixel's feature vector
__device__ float g_vec[BB][CC];                 // partial sum of x*sim
__device__ float g_simsum[BB];                  // partial sum of sim
__device__ unsigned long long g_amax[BB];       // packed (score_bits<<32)|(~idx)
__device__ float g_score[BB * NPIX];            // running score (4 MB)

// ---------------- helpers ----------------
__device__ __forceinline__ unsigned long long pack_score(float s, int n) {
    // score >= 0 always -> float bit pattern is order-preserving.
    // invert index so ties resolve to LOWEST index (matches jnp.argmax).
    return ((unsigned long long)__float_as_uint(s) << 32) |
           (unsigned long long)(0xFFFFFFFFu - (unsigned)n);
}

// ---------------- kernel 1: zero selectedPos + reset amax ----------------
__global__ void zero_kernel(float* __restrict__ selPos) {
    int i = blockIdx.x * blockDim.x + threadIdx.x;      // grid exactly covers BB*NPIX
    selPos[i] = 0.0f;
    if (blockIdx.x == 0 && threadIdx.x < BB) g_amax[threadIdx.x] = 0ull;
}

// ---------------- kernel 2: argmax of score_init per batch ----------------
__global__ void argmax0_kernel(const float* __restrict__ score) {
    int b = blockIdx.y;
    const float* s = score + (size_t)b * NPIX;
    unsigned long long m = 0ull;
    for (int n = blockIdx.x * blockDim.x + threadIdx.x; n < NPIX;
         n += gridDim.x * blockDim.x) {
        unsigned long long p = pack_score(s[n], n);
        m = (p > m) ? p : m;
    }
    #pragma unroll
    for (int o = 16; o; o >>= 1) {
        unsigned long long t = __shfl_down_sync(0xFFFFFFFFu, m, o);
        m = (t > m) ? t : m;
    }
    __shared__ unsigned long long sm[8];
    int w = threadIdx.x >> 5;
    if ((threadIdx.x & 31) == 0) sm[w] = m;
    __syncthreads();
    if (threadIdx.x == 0) {
        unsigned long long mm = sm[0];
        for (int i = 1; i < (int)(blockDim.x >> 5); i++)
            mm = (sm[i] > mm) ? sm[i] : mm;
        atomicMax(&g_amax[b], mm);
    }
}

// -------- kernel 3: finish previous iter (vec/simsum) + prep next (raw, resets) -----
__global__ void between_kernel(const float* __restrict__ x,
                               float* __restrict__ vecList,
                               int finish_iter, int do_prep) {
    int b = blockIdx.x, c = threadIdx.x;   // 64 threads
    float fin = 0.0f;
    unsigned ind = 0;
    if (finish_iter >= 0)
        fin = g_vec[b][c] / g_simsum[b];
    if (do_prep)
        ind = 0xFFFFFFFFu - (unsigned)(g_amax[b] & 0xFFFFFFFFull);
    __syncthreads();   // all reads of scratch done before resets
    if (finish_iter >= 0)
        vecList[((size_t)b * NBVEC + finish_iter) * CC + c] = fin;
    if (do_prep) {
        g_raw[b][c] = x[((size_t)(b * CC + c)) * NPIX + ind];
        g_vec[b][c] = 0.0f;
        if (c == 0) { g_simsum[b] = 0.0f; g_amax[b] = 0ull; }
    }
}

// ---------------- kernel 4: fused main pass ----------------
// Per pixel n of batch b:
//   d2 = ||x[:,n] - raw||^2 ; sim = exp(-sqrt(max(d2,1e-12))/20)
//   simOut[n] = sim ; acc[c] += x[c,n]*sim ; lsum += sim
//   ns = (1-sim)*score_in[n] ; score_out[n] = ns ; track argmax(ns)
__global__ void __launch_bounds__(256)
main_kernel(const float* __restrict__ x,
            const float* __restrict__ score_init,   // used only when first_iter
            int first_iter,
            float* __restrict__ simList,            // base of simList output
            int iter) {
    const int b = blockIdx.y;
    const float* xb   = x + (size_t)b * CC * NPIX;
    const float* scin = (first_iter ? score_init : (const float*)g_score) + (size_t)b * NPIX;
    float* scout = g_score + (size_t)b * NPIX;
    float* simo  = simList + ((size_t)b * NBVEC + iter) * NPIX;

    __shared__ float sraw[CC];
    if (threadIdx.x < CC) sraw[threadIdx.x] = g_raw[b][threadIdx.x];
    __syncthreads();

    float acc[CC];
    #pragma unroll
    for (int c = 0; c < CC; c++) acc[c] = 0.0f;
    float lsum = 0.0f;
    unsigned long long lmax = 0ull;

    const int stride = gridDim.x * blockDim.x;
    for (int n = blockIdx.x * blockDim.x + threadIdx.x; n < NPIX; n += stride) {
        float v[CC];
        #pragma unroll
        for (int c = 0; c < CC; c++) v[c] = xb[c * NPIX + n];

        float d2 = 0.0f;
        #pragma unroll
        for (int c = 0; c < CC; c++) {
            float d = v[c] - sraw[c];
            d2 = fmaf(d, d, d2);
        }
        // precise expf/sqrtf: keep score within ~1e-7 of XLA so argmax doesn't flip
        float sim = expf(-sqrtf(fmaxf(d2, 1e-12f)) * INV_TEMP);

        simo[n] = sim;
        #pragma unroll
        for (int c = 0; c < CC; c++) acc[c] = fmaf(v[c], sim, acc[c]);
        lsum += sim;

        float ns = (1.0f - sim) * scin[n];
        scout[n] = ns;
        unsigned long long p = pack_score(ns, n);
        lmax = (p > lmax) ? p : lmax;
    }

    // warp reduce
    #pragma unroll
    for (int c = 0; c < CC; c++) {
        #pragma unroll
        for (int o = 16; o; o >>= 1)
            acc[c] += __shfl_down_sync(0xFFFFFFFFu, acc[c], o);
    }
    #pragma unroll
    for (int o = 16; o; o >>= 1) {
        lsum += __shfl_down_sync(0xFFFFFFFFu, lsum, o);
        unsigned long long t = __shfl_down_sync(0xFFFFFFFFu, lmax, o);
        lmax = (t > lmax) ? t : lmax;
    }

    __shared__ float swacc[8][CC];
    __shared__ float swsum[8];
    __shared__ unsigned long long swmax[8];
    int w = threadIdx.x >> 5;
    if ((threadIdx.x & 31) == 0) {
        #pragma unroll
        for (int c = 0; c < CC; c++) swacc[w][c] = acc[c];
        swsum[w] = lsum;
        swmax[w] = lmax;
    }
    __syncthreads();
    if (threadIdx.x < CC) {
        float a = 0.0f;
        #pragma unroll
        for (int ww = 0; ww < 8; ww++) a += swacc[ww][threadIdx.x];
        atomicAdd(&g_vec[b][threadIdx.x], a);
    }
    if (threadIdx.x == 0) {
        float s = 0.0f;
        unsigned long long m = 0ull;
        #pragma unroll
        for (int ww = 0; ww < 8; ww++) {
            s += swsum[ww];
            m = (swmax[ww] > m) ? swmax[ww] : m;
        }
        atomicAdd(&g_simsum[b], s);
        atomicMax(&g_amax[b], m);
    }
}

// ---------------- launcher ----------------
extern "C" void kernel_launch(void* const* d_in, const int* in_sizes, int n_in,
                              void* d_out, int out_size) {
    const float* x          = (const float*)d_in[0];   // [16,64,256,256]
    const float* score_init = (const float*)d_in[1];   // [16,65536]
    float* out = (float*)d_out;

    float* vecList = out;                                            // 16*4*64
    float* simList = out + (size_t)BB * NBVEC * CC;                  // 16*4*65536
    float* selPos  = simList + (size_t)BB * NBVEC * NPIX;            // 16*65536

    zero_kernel<<<(BB * NPIX) / 256, 256>>>(selPos);
    argmax0_kernel<<<dim3(32, BB), 256>>>(score_init);
    between_kernel<<<BB, CC>>>(x, vecList, /*finish_iter=*/-1, /*do_prep=*/1);

    for (int it = 0; it < NBVEC; ++it) {
        main_kernel<<<dim3(64, BB), 256>>>(x, score_init, it == 0 ? 1 : 0,
                                           simList, it);
        int do_prep = (it + 1 < NBVEC) ? 1 : 0;
        between_kernel<<<BB, CC>>>(x, vecList, /*finish_iter=*/it, do_prep);
    }
}

// round 2
// speedup vs baseline: 1.5277x; 1.5277x over previous
#include <cuda_runtime.h>
#include <cstdint>

#define BB 16
#define CC 64
#define NPIX 65536          // 256*256
#define NBVEC 4
#define INV_TEMP (1.0f/20.0f)

// ---------------- device scratch (no allocations allowed) ----------------
__device__ float g_raw[BB][CC];                 // selected pixel's feature vector
__device__ float g_vec[BB][CC];                 // partial sum of x*sim
__device__ float g_simsum[BB];                  // partial sum of sim
__device__ unsigned long long g_amax[BB];       // packed (score_bits<<32)|(~idx)
__device__ float g_score[BB * NPIX];            // running score (4 MB)

// ---------------- helpers ----------------
__device__ __forceinline__ unsigned long long pack_score(float s, int n) {
    // score >= 0 always -> float bit pattern is order-preserving.
    // invert index so ties resolve to LOWEST index (matches jnp.argmax).
    return ((unsigned long long)__float_as_uint(s) << 32) |
           (unsigned long long)(0xFFFFFFFFu - (unsigned)n);
}

// ---------------- kernel 1: zero selectedPos + reset amax ----------------
__global__ void zero_kernel(float* __restrict__ selPos) {
    int i = blockIdx.x * blockDim.x + threadIdx.x;      // grid exactly covers BB*NPIX
    selPos[i] = 0.0f;
    if (blockIdx.x == 0 && threadIdx.x < BB) g_amax[threadIdx.x] = 0ull;
}

// ---------------- kernel 2: argmax of score_init per batch ----------------
__global__ void argmax0_kernel(const float* __restrict__ score) {
    int b = blockIdx.y;
    const float* s = score + (size_t)b * NPIX;
    unsigned long long m = 0ull;
    for (int n = blockIdx.x * blockDim.x + threadIdx.x; n < NPIX;
         n += gridDim.x * blockDim.x) {
        unsigned long long p = pack_score(s[n], n);
        m = (p > m) ? p : m;
    }
    #pragma unroll
    for (int o = 16; o; o >>= 1) {
        unsigned long long t = __shfl_down_sync(0xFFFFFFFFu, m, o);
        m = (t > m) ? t : m;
    }
    __shared__ unsigned long long sm[8];
    int w = threadIdx.x >> 5;
    if ((threadIdx.x & 31) == 0) sm[w] = m;
    __syncthreads();
    if (threadIdx.x == 0) {
        unsigned long long mm = sm[0];
        for (int i = 1; i < (int)(blockDim.x >> 5); i++)
            mm = (sm[i] > mm) ? sm[i] : mm;
        atomicMax(&g_amax[b], mm);
    }
}

// -------- kernel 3: finish previous iter (vec/simsum) + prep next (raw, resets) -----
__global__ void between_kernel(const float* __restrict__ x,
                               float* __restrict__ vecList,
                               int finish_iter, int do_prep) {
    int b = blockIdx.x, c = threadIdx.x;   // 64 threads
    float fin = 0.0f;
    unsigned ind = 0;
    if (finish_iter >= 0)
        fin = g_vec[b][c] / g_simsum[b];
    if (do_prep)
        ind = 0xFFFFFFFFu - (unsigned)(g_amax[b] & 0xFFFFFFFFull);
    __syncthreads();   // all reads of scratch done before resets
    if (finish_iter >= 0)
        vecList[((size_t)b * NBVEC + finish_iter) * CC + c] = fin;
    if (do_prep) {
        g_raw[b][c] = x[((size_t)(b * CC + c)) * NPIX + ind];
        g_vec[b][c] = 0.0f;
        if (c == 0) { g_simsum[b] = 0.0f; g_amax[b] = 0ull; }
    }
}

// ---------------- kernel 4: fused main pass (channel-split, float4) ----------------
// blockDim 256 = 4 channel-groups (cg) x 64 lanes. Each thread: 16 channels,
// 4 consecutive pixels (float4). Per tile a block covers 256 pixels.
__global__ void __launch_bounds__(256, 2)
main_kernel(const float* __restrict__ x,
            const float* __restrict__ score_init,   // used only when first_iter
            int first_iter,
            float* __restrict__ simList,            // base of simList output
            int iter) {
    const int b  = blockIdx.y;
    const int t  = threadIdx.x;
    const int cg = t >> 6;          // 0..3  (channels cg*16 .. cg*16+15)
    const int l  = t & 63;          // 0..63 (pixel quad within tile)

    const float* xb   = x + (size_t)b * CC * NPIX + (size_t)cg * 16 * NPIX;
    const float* scin = (first_iter ? score_init : (const float*)g_score) + (size_t)b * NPIX;
    float* scout = g_score + (size_t)b * NPIX;
    float* simo  = simList + ((size_t)b * NBVEC + iter) * NPIX;

    __shared__ float  sraw[CC];
    __shared__ float4 sd2[4][64];
    if (t < CC) sraw[t] = g_raw[b][t];
    __syncthreads();

    float acc[16];
    #pragma unroll
    for (int i = 0; i < 16; i++) acc[i] = 0.0f;
    float lsum = 0.0f;
    unsigned long long lmax = 0ull;

    for (int tile = blockIdx.x; tile < NPIX / 256; tile += gridDim.x) {
        const int n0 = tile * 256 + l * 4;

        float4 v[16];
        #pragma unroll
        for (int i = 0; i < 16; i++)
            v[i] = *(const float4*)(xb + (size_t)i * NPIX + n0);

        // partial d2 over this thread's 16 channels (4 independent chains)
        float4 d2 = make_float4(0.f, 0.f, 0.f, 0.f);
        #pragma unroll
        for (int i = 0; i < 16; i++) {
            float r = sraw[cg * 16 + i];
            float d;
            d = v[i].x - r; d2.x = fmaf(d, d, d2.x);
            d = v[i].y - r; d2.y = fmaf(d, d, d2.y);
            d = v[i].z - r; d2.z = fmaf(d, d, d2.z);
            d = v[i].w - r; d2.w = fmaf(d, d, d2.w);
        }
        sd2[cg][l] = d2;
        __syncthreads();
        {
            float4 p0 = sd2[0][l], p1 = sd2[1][l], p2 = sd2[2][l], p3 = sd2[3][l];
            d2.x = (p0.x + p1.x) + (p2.x + p3.x);
            d2.y = (p0.y + p1.y) + (p2.y + p3.y);
            d2.z = (p0.z + p1.z) + (p2.z + p3.z);
            d2.w = (p0.w + p1.w) + (p2.w + p3.w);
        }
        __syncthreads();   // safe to overwrite sd2 next tile

        float4 sim;
        sim.x = expf(-sqrtf(fmaxf(d2.x, 1e-12f)) * INV_TEMP);
        sim.y = expf(-sqrtf(fmaxf(d2.y, 1e-12f)) * INV_TEMP);
        sim.z = expf(-sqrtf(fmaxf(d2.z, 1e-12f)) * INV_TEMP);
        sim.w = expf(-sqrtf(fmaxf(d2.w, 1e-12f)) * INV_TEMP);

        #pragma unroll
        for (int i = 0; i < 16; i++) {
            acc[i] = fmaf(v[i].x, sim.x, acc[i]);
            acc[i] = fmaf(v[i].y, sim.y, acc[i]);
            acc[i] = fmaf(v[i].z, sim.z, acc[i]);
            acc[i] = fmaf(v[i].w, sim.w, acc[i]);
        }

        if (cg == 0) {
            *(float4*)(simo + n0) = sim;
            lsum += (sim.x + sim.y) + (sim.z + sim.w);
        } else if (cg == 1) {
            float4 sc = *(const float4*)(scin + n0);
            float4 ns;
            ns.x = (1.0f - sim.x) * sc.x;
            ns.y = (1.0f - sim.y) * sc.y;
            ns.z = (1.0f - sim.z) * sc.z;
            ns.w = (1.0f - sim.w) * sc.w;
            *(float4*)(scout + n0) = ns;
            unsigned long long p;
            p = pack_score(ns.x, n0 + 0); lmax = (p > lmax) ? p : lmax;
            p = pack_score(ns.y, n0 + 1); lmax = (p > lmax) ? p : lmax;
            p = pack_score(ns.z, n0 + 2); lmax = (p > lmax) ? p : lmax;
            p = pack_score(ns.w, n0 + 3); lmax = (p > lmax) ? p : lmax;
        }
    }

    // ---- reductions: each warp has a single cg; reduce within warp, then atomics
    #pragma unroll
    for (int i = 0; i < 16; i++) {
        float a = acc[i];
        #pragma unroll
        for (int o = 16; o; o >>= 1)
            a += __shfl_down_sync(0xFFFFFFFFu, a, o);
        if ((t & 31) == 0)
            atomicAdd(&g_vec[b][cg * 16 + i], a);
    }
    if (cg == 0) {
        #pragma unroll
        for (int o = 16; o; o >>= 1)
            lsum += __shfl_down_sync(0xFFFFFFFFu, lsum, o);
        if ((t & 31) == 0) atomicAdd(&g_simsum[b], lsum);
    } else if (cg == 1) {
        #pragma unroll
        for (int o = 16; o; o >>= 1) {
            unsigned long long m = __shfl_down_sync(0xFFFFFFFFu, lmax, o);
            lmax = (m > lmax) ? m : lmax;
        }
        if ((t & 31) == 0) atomicMax(&g_amax[b], lmax);
    }
}

// ---------------- launcher ----------------
extern "C" void kernel_launch(void* const* d_in, const int* in_sizes, int n_in,
                              void* d_out, int out_size) {
    const float* x          = (const float*)d_in[0];   // [16,64,256,256]
    const float* score_init = (const float*)d_in[1];   // [16,65536]
    float* out = (float*)d_out;

    float* vecList = out;                                            // 16*4*64
    float* simList = out + (size_t)BB * NBVEC * CC;                  // 16*4*65536
    float* selPos  = simList + (size_t)BB * NBVEC * NPIX;            // 16*65536

    zero_kernel<<<(BB * NPIX) / 256, 256>>>(selPos);
    argmax0_kernel<<<dim3(32, BB), 256>>>(score_init);
    between_kernel<<<BB, CC>>>(x, vecList, /*finish_iter=*/-1, /*do_prep=*/1);

    for (int it = 0; it < NBVEC; ++it) {
        // 18 blocks/batch * 16 batches = 288 blocks = one full resident wave @2 CTA/SM
        main_kernel<<<dim3(18, BB), 256>>>(x, score_init, it == 0 ? 1 : 0,
                                           simList, it);
        int do_prep = (it + 1 < NBVEC) ? 1 : 0;
        between_kernel<<<BB, CC>>>(x, vecList, /*finish_iter=*/it, do_prep);
    }
}